// round 13
// baseline (speedup 1.0000x reference)
#include <cuda_runtime.h>
#include <cuda_bf16.h>
#include <math.h>
#include <stdint.h>

#define B 2
#define S 2048
#define D 1024
#define H 16
#define DH 64
#define BS (B*S)     /* 4096 */
#define D3 (3*D)     /* 3072 */
#define NCH 16       /* key chunks */
#define CHK 128      /* keys per chunk */

// Scratch (allocation-free rule: __device__ globals)
__device__ float g_part[(size_t)NCH * BS * D];   // 256 MB
__device__ float g_lpart[(size_t)NCH * BS * H];  // 4 MB
__device__ float g_cost[S * 32];
__device__ float g_sint[S * 32];
__device__ __nv_bfloat16 g_xhi[BS * D],  g_xlo[BS * D];
__device__ __nv_bfloat16 g_wqT_hi[D3 * D], g_wqT_lo[D3 * D];
__device__ __nv_bfloat16 g_woT_hi[D * D],  g_woT_lo[D * D];
__device__ __nv_bfloat16 g_ahi[BS * D],  g_alo[BS * D];
// roped q,k and v, split bf16, layout [b][h][s][64]
__device__ __nv_bfloat16 g_sqh[BS * D], g_sql[BS * D];
__device__ __nv_bfloat16 g_skh[BS * D], g_skl[BS * D];
__device__ __nv_bfloat16 g_svh[BS * D], g_svl[BS * D];

// ============================================================================
// Helpers
// ============================================================================
__device__ __forceinline__ uint32_t smem_u32(const void* p) {
    uint32_t a;
    asm("{ .reg .u64 t; cvta.to.shared.u64 t, %1; cvt.u32.u64 %0, t; }"
        : "=r"(a) : "l"(p));
    return a;
}
__device__ __forceinline__ void bsplit(float v, __nv_bfloat16& h, __nv_bfloat16& l) {
    h = __float2bfloat16(v);
    l = __float2bfloat16(v - __bfloat162float(h));
}
__device__ __forceinline__ uint32_t packbf(float a, float b) {
    __nv_bfloat162 t = __floats2bfloat162_rn(a, b);
    return *(uint32_t*)&t;
}
__device__ __forceinline__ void cpa16(uint32_t s, const void* g) {
    uint64_t ga;
    asm("cvta.to.global.u64 %0, %1;" : "=l"(ga) : "l"(g));
    asm volatile("cp.async.cg.shared.global [%0], [%1], 16;"
                 :: "r"(s), "l"(ga) : "memory");
}
__device__ __forceinline__ void mma16(float* d, const uint32_t* a,
                                      uint32_t b0, uint32_t b1) {
    asm volatile(
        "mma.sync.aligned.m16n8k16.row.col.f32.bf16.bf16.f32 "
        "{%0,%1,%2,%3}, {%4,%5,%6,%7}, {%8,%9}, {%0,%1,%2,%3};"
        : "+f"(d[0]), "+f"(d[1]), "+f"(d[2]), "+f"(d[3])
        : "r"(a[0]), "r"(a[1]), "r"(a[2]), "r"(a[3]), "r"(b0), "r"(b1));
}
#define LDM4(r, addr) \
    asm volatile("ldmatrix.sync.aligned.m8n8.x4.shared.b16 {%0,%1,%2,%3}, [%4];" \
        : "=r"((r)[0]), "=r"((r)[1]), "=r"((r)[2]), "=r"((r)[3]) : "r"(addr))
#define LDM4T(r, addr) \
    asm volatile("ldmatrix.sync.aligned.m8n8.x4.trans.shared.b16 {%0,%1,%2,%3}, [%4];" \
        : "=r"((r)[0]), "=r"((r)[1]), "=r"((r)[2]), "=r"((r)[3]) : "r"(addr))

// ============================================================================
// Split kernels
// ============================================================================
__global__ void split_kernel(const float* __restrict__ src,
                             __nv_bfloat16* __restrict__ hi,
                             __nv_bfloat16* __restrict__ lo, int n4)
{
    int i = blockIdx.x * blockDim.x + threadIdx.x;
    if (i >= n4) return;
    float4 v = ((const float4*)src)[i];
    __nv_bfloat16 h0,h1,h2,h3,l0,l1,l2,l3;
    bsplit(v.x,h0,l0); bsplit(v.y,h1,l1); bsplit(v.z,h2,l2); bsplit(v.w,h3,l3);
    __nv_bfloat162 hp0, hp1, lp0, lp1;
    hp0.x=h0; hp0.y=h1; hp1.x=h2; hp1.y=h3;
    lp0.x=l0; lp0.y=l1; lp1.x=l2; lp1.y=l3;
    ((__nv_bfloat162*)hi)[2*i] = hp0; ((__nv_bfloat162*)hi)[2*i+1] = hp1;
    ((__nv_bfloat162*)lo)[2*i] = lp0; ((__nv_bfloat162*)lo)[2*i+1] = lp1;
}

__global__ void tsplit_kernel(const float* __restrict__ src,
                              __nv_bfloat16* __restrict__ dhi,
                              __nv_bfloat16* __restrict__ dlo, int R, int C)
{
    __shared__ float t[32][33];
    int c0 = blockIdx.x * 32, r0 = blockIdx.y * 32;
    int x = threadIdx.x, y = threadIdx.y;
    #pragma unroll
    for (int i = 0; i < 32; i += 8)
        t[y + i][x] = src[(size_t)(r0 + y + i) * C + c0 + x];
    __syncthreads();
    #pragma unroll
    for (int i = 0; i < 32; i += 8) {
        float v = t[x][y + i];
        __nv_bfloat16 h, l; bsplit(v, h, l);
        size_t o = (size_t)(c0 + y + i) * R + r0 + x;
        dhi[o] = h; dlo[o] = l;
    }
}

// ============================================================================
// 3xBF16 mma GEMM. CTA tile 128x64, BK=32, 256 threads = 8 warps (4x2),
// warp tile 32x32, 3-stage cp.async. 92 KB smem + ~23K regs per CTA
// -> 2 CTAs/SM co-resident (independent barriers stagger the stage syncs).
// mode 0: plain fp32 C.  mode 1: fused rope+split epilogue (one head/CTA).
// ============================================================================
#define STG 30720
#define OFF_AHI 0
#define OFF_ALO 10240
#define OFF_BHI 20480
#define OFF_BLO 25600
#define GSMEM (3 * STG)   /* 92160 */
#define STF 68            /* fp32 staging stride (floats), 64 cols + pad */

__global__ __launch_bounds__(256) void gemm_bf16x3_kernel(
    const __nv_bfloat16* __restrict__ Ahi, const __nv_bfloat16* __restrict__ Alo,
    const __nv_bfloat16* __restrict__ Bhi, const __nv_bfloat16* __restrict__ Blo,
    float* __restrict__ C, int M, int N, int K, int mode)
{
    extern __shared__ char smc[];
    const uint32_t sb = smem_u32(smc);
    const int tid = threadIdx.x, lane = tid & 31, wid = tid >> 5;
    const int wm = wid & 3, wn = wid >> 2;            // 4 x 2 warps
    const int tg = lane & 3, gp = lane >> 2;
    const int m0 = blockIdx.y * 128, n0 = blockIdx.x * 64;
    const uint32_t lrow = ((lane & 7) + ((lane >> 3) & 1) * 8) * 80
                        + (lane >> 4) * 16;
    const int ra = tid >> 1, ca = (tid & 1) * 2;      // A: 2 chunks/thread
    const int rb = tid >> 2, cb = tid & 3;            // B: 1 chunk/thread

    float acc[2][4][4];
    #pragma unroll
    for (int mi = 0; mi < 2; mi++)
        #pragma unroll
        for (int ni = 0; ni < 4; ni++)
            #pragma unroll
            for (int c = 0; c < 4; c++) acc[mi][ni][c] = 0.f;

    #define ISSUE(st, k0) {                                                     \
        uint32_t base = sb + (st) * STG;                                        \
        size_t goA = (size_t)(m0 + ra) * K + (k0) + ca * 8;                     \
        uint32_t sA = base + ra * 80 + ca * 16;                                 \
        cpa16(sA + OFF_AHI,      Ahi + goA);                                    \
        cpa16(sA + OFF_AHI + 16, Ahi + goA + 8);                                \
        cpa16(sA + OFF_ALO,      Alo + goA);                                    \
        cpa16(sA + OFF_ALO + 16, Alo + goA + 8);                                \
        size_t goB = (size_t)(n0 + rb) * K + (k0) + cb * 8;                     \
        uint32_t sB = base + rb * 80 + cb * 16;                                 \
        cpa16(sB + OFF_BHI, Bhi + goB);                                         \
        cpa16(sB + OFF_BLO, Blo + goB); }

    #define CMT asm volatile("cp.async.commit_group;" ::: "memory")

    ISSUE(0, 0);  CMT;
    ISSUE(1, 32); CMT;

    const int nst = K / 32;
    for (int s = 0; s < nst; s++) {
        asm volatile("cp.async.wait_group 1;" ::: "memory");
        __syncthreads();
        if (s + 2 < nst) { ISSUE((s + 2) % 3, (s + 2) * 32); }
        CMT;

        const uint32_t sbase = sb + (s % 3) * STG;
        #pragma unroll
        for (int ks = 0; ks < 2; ks++) {
            uint32_t Ah[2][4], Al[2][4], Bh[2][4], Bl[2][4];
            const uint32_t kso = ks * 32 + lrow;
            #pragma unroll
            for (int mi = 0; mi < 2; mi++) {
                uint32_t ro = (wm * 32 + mi * 16) * 80 + kso;
                LDM4(Ah[mi], sbase + OFF_AHI + ro);
                LDM4(Al[mi], sbase + OFF_ALO + ro);
            }
            #pragma unroll
            for (int g = 0; g < 2; g++) {
                uint32_t ro = (wn * 32 + g * 16) * 80 + kso;
                LDM4(Bh[g], sbase + OFF_BHI + ro);
                LDM4(Bl[g], sbase + OFF_BLO + ro);
            }
            #pragma unroll
            for (int mi = 0; mi < 2; mi++)
                #pragma unroll
                for (int ni = 0; ni < 4; ni++) {
                    const int g = ni >> 1, sl = ni & 1;
                    float* dd = acc[mi][ni];
                    mma16(dd, Ah[mi], Bh[g][sl], Bh[g][sl + 2]);
                    mma16(dd, Ah[mi], Bl[g][sl], Bl[g][sl + 2]);
                    mma16(dd, Al[mi], Bh[g][sl], Bh[g][sl + 2]);
                }
        }
    }

    if (mode == 0) {
        #pragma unroll
        for (int mi = 0; mi < 2; mi++) {
            int row = m0 + wm * 32 + mi * 16 + gp;
            #pragma unroll
            for (int ni = 0; ni < 4; ni++) {
                int col = n0 + wn * 32 + ni * 8 + 2 * tg;
                *(float2*)&C[(size_t)row * N + col] =
                    make_float2(acc[mi][ni][0], acc[mi][ni][1]);
                *(float2*)&C[(size_t)(row + 8) * N + col] =
                    make_float2(acc[mi][ni][2], acc[mi][ni][3]);
            }
        }
    } else {
        // Fused rope + hi/lo split epilogue. This CTA's 64 columns are exactly
        // one head of one region (q/k/v).
        __syncthreads();
        float* st = (float*)smc;
        #pragma unroll
        for (int mi = 0; mi < 2; mi++) {
            int row = wm * 32 + mi * 16 + gp;
            #pragma unroll
            for (int ni = 0; ni < 4; ni++) {
                int col = wn * 32 + ni * 8 + 2 * tg;
                *(float2*)&st[row * STF + col] =
                    make_float2(acc[mi][ni][0], acc[mi][ni][1]);
                *(float2*)&st[(row + 8) * STF + col] =
                    make_float2(acc[mi][ni][2], acc[mi][ni][3]);
            }
        }
        __syncthreads();

        const int region = n0 >> 10;            // 0=q 1=k 2=v
        const int hh     = (n0 & 1023) >> 6;    // head

        // 128 rows x 32 pairs = 4096 work items
        for (int e = tid; e < 4096; e += 256) {
            int row = e >> 5;
            int i   = e & 31;
            int grow = m0 + row;
            int s    = grow & (S - 1);
            int b    = grow >> 11;

            float v1 = st[row * STF + i];
            float v2 = st[row * STF + i + 32];
            size_t o = ((size_t)(b * H + hh) * S + s) * 64 + i;
            __nv_bfloat16 ph, pl;

            if (region == 2) {
                bsplit(v1, ph, pl); g_svh[o] = ph;      g_svl[o] = pl;
                bsplit(v2, ph, pl); g_svh[o + 32] = ph; g_svl[o + 32] = pl;
            } else {
                float c  = g_cost[(s << 5) + i];
                float sn = g_sint[(s << 5) + i];
                float r1v = v1 * c - v2 * sn;
                float r2v = v1 * sn + v2 * c;
                if (region == 0) {
                    bsplit(r1v, ph, pl); g_sqh[o] = ph;      g_sql[o] = pl;
                    bsplit(r2v, ph, pl); g_sqh[o + 32] = ph; g_sql[o + 32] = pl;
                } else {
                    bsplit(r1v, ph, pl); g_skh[o] = ph;      g_skl[o] = pl;
                    bsplit(r2v, ph, pl); g_skh[o + 32] = ph; g_skl[o + 32] = pl;
                }
            }
        }
    }
    #undef ISSUE
    #undef CMT
}

// ============================================================================
// RoPE tables (fp32)
// ============================================================================
__global__ void rope_table_kernel()
{
    int idx = blockIdx.x * blockDim.x + threadIdx.x;
    if (idx >= S * 32) return;
    int i = idx & 31;
    int s = idx >> 5;
    float inv = 1.0f / powf(10000.0f, (float)(2 * i) / 64.0f);
    float ang = (float)s * inv;
    float sn, c;
    sincosf(ang, &sn, &c);
    g_cost[idx] = c;
    g_sint[idx] = sn;
}

// ============================================================================
// Tensor-core split-KV flash (frozen R10 config: CHK=128, single KV buffer).
// ============================================================================
#define FSTR 144
#define FT (128 * FSTR)
#define FOQH (0 * FT)
#define FOQL (1 * FT)
#define FOKH (2 * FT)
#define FOKL (3 * FT)
#define FOVH (4 * FT)
#define FOVL (5 * FT)
#define FOMSK (6 * FT)
#define FSMEM (6 * FT + 128)

__global__ __launch_bounds__(256) void flash_mma_kernel(
    const unsigned char* __restrict__ mask, const int* __restrict__ is_causal_p)
{
    extern __shared__ char smc[];
    const uint32_t sb = smem_u32(smc);

    const int qt = blockIdx.x;
    const int ch = blockIdx.y;
    const int bz = blockIdx.z;
    const int b  = bz >> 4;
    const int h  = bz & (H - 1);
    const bool causal = (*is_causal_p) != 0;
    if (causal && ch > qt) return;

    const int tid = threadIdx.x, lane = tid & 31, wid = tid >> 5;
    const int tg = lane & 3, gp = lane >> 2;
    const float scale = 0.125f;

    const size_t qb = ((size_t)bz * S + qt * 128) * 64;
    const size_t kb = ((size_t)bz * S + ch * 128) * 64;
    for (int t = tid; t < 1024; t += 256) {
        int r = t >> 3, c = t & 7;
        uint32_t dst = sb + r * FSTR + c * 16;
        size_t go = (size_t)r * 64 + c * 8;
        cpa16(dst + FOQH, g_sqh + qb + go);
        cpa16(dst + FOQL, g_sql + qb + go);
        cpa16(dst + FOKH, g_skh + kb + go);
        cpa16(dst + FOKL, g_skl + kb + go);
        cpa16(dst + FOVH, g_svh + kb + go);
        cpa16(dst + FOVL, g_svl + kb + go);
    }
    asm volatile("cp.async.commit_group;" ::: "memory");
    if (!causal && tid < 128)
        *(unsigned char*)(smc + FOMSK + tid) = mask[b * S + ch * 128 + tid];
    asm volatile("cp.async.wait_group 0;" ::: "memory");
    __syncthreads();

    const uint32_t lrowA = ((lane & 7) + ((lane >> 3) & 1) * 8) * FSTR
                         + (lane >> 4) * 16;

    uint32_t Qh[4][4], Ql[4][4];
    #pragma unroll
    for (int ks = 0; ks < 4; ks++) {
        uint32_t ro = (wid * 16) * FSTR + ks * 32 + lrowA;
        LDM4(Qh[ks], sb + FOQH + ro);
        LDM4(Ql[ks], sb + FOQL + ro);
    }

    float acc[16][4];
    #pragma unroll
    for (int ni = 0; ni < 16; ni++)
        #pragma unroll
        for (int c = 0; c < 4; c++) acc[ni][c] = 0.f;

    #pragma unroll
    for (int g = 0; g < 8; g++) {
        #pragma unroll
        for (int ks = 0; ks < 4; ks++) {
            uint32_t Kh4[4], Kl4[4];
            uint32_t ro = (g * 16) * FSTR + ks * 32 + lrowA;
            LDM4(Kh4, sb + FOKH + ro);
            LDM4(Kl4, sb + FOKL + ro);
            #pragma unroll
            for (int sl = 0; sl < 2; sl++) {
                float* dd = acc[g * 2 + sl];
                mma16(dd, Qh[ks], Kh4[sl], Kh4[sl + 2]);
                mma16(dd, Qh[ks], Kl4[sl], Kl4[sl + 2]);
                mma16(dd, Ql[ks], Kh4[sl], Kh4[sl + 2]);
            }
        }
    }

    const int qi0 = qt * 128 + wid * 16 + gp;
    float l0 = 0.f, l1 = 0.f;
    #pragma unroll
    for (int ni = 0; ni < 16; ni++) {
        #pragma unroll
        for (int e = 0; e < 2; e++) {
            int colg = ch * 128 + ni * 8 + 2 * tg + e;
            bool mv = causal ? true
                             : (*(unsigned char*)(smc + FOMSK + ni*8 + 2*tg + e) != 0);
            float p0 = (causal ? (colg <= qi0)     : mv)
                       ? __expf(acc[ni][e] * scale) : 0.f;
            float p1 = (causal ? (colg <= qi0 + 8) : mv)
                       ? __expf(acc[ni][e + 2] * scale) : 0.f;
            acc[ni][e] = p0; acc[ni][e + 2] = p1;
            l0 += p0; l1 += p1;
        }
    }
    l0 += __shfl_xor_sync(0xFFFFFFFF, l0, 1);
    l0 += __shfl_xor_sync(0xFFFFFFFF, l0, 2);
    l1 += __shfl_xor_sync(0xFFFFFFFF, l1, 1);
    l1 += __shfl_xor_sync(0xFFFFFFFF, l1, 2);
    if (tg == 0) {
        g_lpart[((size_t)ch * BS + b * S + qi0)     * H + h] = l0;
        g_lpart[((size_t)ch * BS + b * S + qi0 + 8) * H + h] = l1;
    }

    float accv[8][4];
    #pragma unroll
    for (int ni = 0; ni < 8; ni++)
        #pragma unroll
        for (int c = 0; c < 4; c++) accv[ni][c] = 0.f;

    #pragma unroll
    for (int kt = 0; kt < 8; kt++) {
        uint32_t Ph[4], Pl[4];
        #pragma unroll
        for (int half = 0; half < 2; half++) {
            const float* a = acc[2 * kt + half];
            #pragma unroll
            for (int rr = 0; rr < 2; rr++) {
                float pa = a[rr * 2], pb = a[rr * 2 + 1];
                __nv_bfloat16 ha = __float2bfloat16(pa);
                __nv_bfloat16 hb = __float2bfloat16(pb);
                float la = pa - __bfloat162float(ha);
                float lb = pb - __bfloat162float(hb);
                __nv_bfloat162 hp; hp.x = ha; hp.y = hb;
                Ph[half * 2 + rr] = *(uint32_t*)&hp;
                Pl[half * 2 + rr] = packbf(la, lb);
            }
        }
        #pragma unroll
        for (int g2 = 0; g2 < 4; g2++) {
            uint32_t Vh4[4], Vl4[4];
            uint32_t ro = (kt * 16 + (lane & 15)) * FSTR
                        + g2 * 32 + (lane >> 4) * 16;
            LDM4T(Vh4, sb + FOVH + ro);
            LDM4T(Vl4, sb + FOVL + ro);
            #pragma unroll
            for (int sl = 0; sl < 2; sl++) {
                float* dd = accv[g2 * 2 + sl];
                mma16(dd, Ph, Vh4[sl * 2], Vh4[sl * 2 + 1]);
                mma16(dd, Ph, Vl4[sl * 2], Vl4[sl * 2 + 1]);
                mma16(dd, Pl, Vh4[sl * 2], Vh4[sl * 2 + 1]);
            }
        }
    }

    float* p0 = g_part + ((size_t)ch * BS + b * S + qi0)     * D + h * DH;
    float* p1 = g_part + ((size_t)ch * BS + b * S + qi0 + 8) * D + h * DH;
    #pragma unroll
    for (int ni = 0; ni < 8; ni++) {
        int d = ni * 8 + 2 * tg;
        *(float2*)(p0 + d) = make_float2(accv[ni][0], accv[ni][1]);
        *(float2*)(p1 + d) = make_float2(accv[ni][2], accv[ni][3]);
    }
}

// ============================================================================
// Reduce partials -> attn as split bf16 (hi/lo)
// ============================================================================
__global__ void flash_reduce_kernel(const int* __restrict__ is_causal_p)
{
    int idx = blockIdx.x * blockDim.x + threadIdx.x;
    if (idx >= BS * D / 4) return;
    int base = idx * 4;
    int qrow = base / D;
    int d    = base % D;
    int h    = d >> 6;
    int q    = qrow & (S - 1);
    const int nv = (*is_causal_p) ? ((q >> 7) + 1) : NCH;

    float4 acc = make_float4(0.f, 0.f, 0.f, 0.f);
    float l = 0.f;
    for (int c = 0; c < nv; c++) {
        const float4 p = *(const float4*)(g_part + ((size_t)c * BS + qrow) * D + d);
        acc.x += p.x; acc.y += p.y; acc.z += p.z; acc.w += p.w;
        l += g_lpart[((size_t)c * BS + qrow) * H + h];
    }
    float inv = 1.f / l;
    float o0 = acc.x*inv, o1 = acc.y*inv, o2 = acc.z*inv, o3 = acc.w*inv;

    __nv_bfloat16 h0,h1,h2,h3,l0,l1,l2,l3;
    bsplit(o0,h0,l0); bsplit(o1,h1,l1); bsplit(o2,h2,l2); bsplit(o3,h3,l3);
    size_t o = (size_t)qrow * D + d;
    __nv_bfloat162 t;
    t.x=h0; t.y=h1; *(__nv_bfloat162*)(g_ahi + o)     = t;
    t.x=h2; t.y=h3; *(__nv_bfloat162*)(g_ahi + o + 2) = t;
    t.x=l0; t.y=l1; *(__nv_bfloat162*)(g_alo + o)     = t;
    t.x=l2; t.y=l3; *(__nv_bfloat162*)(g_alo + o + 2) = t;
}

// ============================================================================
extern "C" void kernel_launch(void* const* d_in, const int* in_sizes, int n_in,
                              void* d_out, int out_size)
{
    const float* x      = (const float*)d_in[0];
    const float* qkv_w  = (const float*)d_in[1];
    const float* out_w  = (const float*)d_in[2];
    const unsigned char* mask = (const unsigned char*)d_in[3];
    const int* is_causal = (const int*)d_in[4];
    float* out = (float*)d_out;

    __nv_bfloat16 *xhi, *xlo, *wqh, *wql, *woh, *wol, *ahi, *alo;
    cudaGetSymbolAddress((void**)&xhi, g_xhi);
    cudaGetSymbolAddress((void**)&xlo, g_xlo);
    cudaGetSymbolAddress((void**)&wqh, g_wqT_hi);
    cudaGetSymbolAddress((void**)&wql, g_wqT_lo);
    cudaGetSymbolAddress((void**)&woh, g_woT_hi);
    cudaGetSymbolAddress((void**)&wol, g_woT_lo);
    cudaGetSymbolAddress((void**)&ahi, g_ahi);
    cudaGetSymbolAddress((void**)&alo, g_alo);

    cudaFuncSetAttribute(gemm_bf16x3_kernel,
                         cudaFuncAttributeMaxDynamicSharedMemorySize, GSMEM);
    cudaFuncSetAttribute(flash_mma_kernel,
                         cudaFuncAttributeMaxDynamicSharedMemorySize, FSMEM);

    // 0) Pre-splits + rope table (table must precede the fused QKV epilogue)
    split_kernel<<<(BS * D / 4 + 255) / 256, 256>>>(x, xhi, xlo, BS * D / 4);
    tsplit_kernel<<<dim3(D3 / 32, D / 32), dim3(32, 8)>>>(qkv_w, wqh, wql, D, D3);
    tsplit_kernel<<<dim3(D  / 32, D / 32), dim3(32, 8)>>>(out_w, woh, wol, D, D);
    rope_table_kernel<<<(S * 32 + 255) / 256, 256>>>();

    // 1) QKV projection with fused rope+split epilogue (mode 1)
    gemm_bf16x3_kernel<<<dim3(D3 / 64, BS / 128), 256, GSMEM>>>(
        xhi, xlo, wqh, wql, nullptr, BS, D3, D, 1);

    // 2) Flash (CHK=128) + reduce
    flash_mma_kernel<<<dim3(S / 128, NCH, B * H), 256, FSMEM>>>(mask, is_causal);
    flash_reduce_kernel<<<(BS * D / 4 + 255) / 256, 256>>>(is_causal);

    // 3) Output projection (mode 0)
    gemm_bf16x3_kernel<<<dim3(D / 64, BS / 128), 256, GSMEM>>>(
        ahi, alo, woh, wol, out, BS, D, D, 0);
}

// round 14
// speedup vs baseline: 1.6314x; 1.6314x over previous
#include <cuda_runtime.h>
#include <cuda_bf16.h>
#include <math.h>
#include <stdint.h>

#define B 2
#define S 2048
#define D 1024
#define H 16
#define DH 64
#define BS (B*S)     /* 4096 */
#define D3 (3*D)     /* 3072 */
#define NCH 16       /* key chunks */
#define CHK 128      /* keys per chunk */

// Scratch (allocation-free rule: __device__ globals)
__device__ float g_part[(size_t)NCH * BS * D];   // 256 MB
__device__ float g_lpart[(size_t)NCH * BS * H];  // 4 MB
__device__ float g_cost[S * 32];
__device__ float g_sint[S * 32];
__device__ __nv_bfloat16 g_xhi[BS * D],  g_xlo[BS * D];
__device__ __nv_bfloat16 g_wqT_hi[D3 * D], g_wqT_lo[D3 * D];
__device__ __nv_bfloat16 g_woT_hi[D * D],  g_woT_lo[D * D];
__device__ __nv_bfloat16 g_ahi[BS * D],  g_alo[BS * D];
// roped q,k and v, split bf16, layout [b][h][s][64]
__device__ __nv_bfloat16 g_sqh[BS * D], g_sql[BS * D];
__device__ __nv_bfloat16 g_skh[BS * D], g_skl[BS * D];
__device__ __nv_bfloat16 g_svh[BS * D], g_svl[BS * D];

// ============================================================================
// Helpers
// ============================================================================
__device__ __forceinline__ uint32_t smem_u32(const void* p) {
    uint32_t a;
    asm("{ .reg .u64 t; cvta.to.shared.u64 t, %1; cvt.u32.u64 %0, t; }"
        : "=r"(a) : "l"(p));
    return a;
}
__device__ __forceinline__ void bsplit(float v, __nv_bfloat16& h, __nv_bfloat16& l) {
    h = __float2bfloat16(v);
    l = __float2bfloat16(v - __bfloat162float(h));
}
__device__ __forceinline__ uint32_t packbf(float a, float b) {
    __nv_bfloat162 t = __floats2bfloat162_rn(a, b);
    return *(uint32_t*)&t;
}
__device__ __forceinline__ uint32_t pack2h(__nv_bfloat16 a, __nv_bfloat16 b) {
    __nv_bfloat162 t; t.x = a; t.y = b;
    return *(uint32_t*)&t;
}
__device__ __forceinline__ void cpa16(uint32_t s, const void* g) {
    uint64_t ga;
    asm("cvta.to.global.u64 %0, %1;" : "=l"(ga) : "l"(g));
    asm volatile("cp.async.cg.shared.global [%0], [%1], 16;"
                 :: "r"(s), "l"(ga) : "memory");
}
__device__ __forceinline__ void mma16(float* d, const uint32_t* a,
                                      uint32_t b0, uint32_t b1) {
    asm volatile(
        "mma.sync.aligned.m16n8k16.row.col.f32.bf16.bf16.f32 "
        "{%0,%1,%2,%3}, {%4,%5,%6,%7}, {%8,%9}, {%0,%1,%2,%3};"
        : "+f"(d[0]), "+f"(d[1]), "+f"(d[2]), "+f"(d[3])
        : "r"(a[0]), "r"(a[1]), "r"(a[2]), "r"(a[3]), "r"(b0), "r"(b1));
}
#define LDM4(r, addr) \
    asm volatile("ldmatrix.sync.aligned.m8n8.x4.shared.b16 {%0,%1,%2,%3}, [%4];" \
        : "=r"((r)[0]), "=r"((r)[1]), "=r"((r)[2]), "=r"((r)[3]) : "r"(addr))
#define LDM4T(r, addr) \
    asm volatile("ldmatrix.sync.aligned.m8n8.x4.trans.shared.b16 {%0,%1,%2,%3}, [%4];" \
        : "=r"((r)[0]), "=r"((r)[1]), "=r"((r)[2]), "=r"((r)[3]) : "r"(addr))

// ============================================================================
// Split kernels
// ============================================================================
__global__ void split_kernel(const float* __restrict__ src,
                             __nv_bfloat16* __restrict__ hi,
                             __nv_bfloat16* __restrict__ lo, int n4)
{
    int i = blockIdx.x * blockDim.x + threadIdx.x;
    if (i >= n4) return;
    float4 v = ((const float4*)src)[i];
    __nv_bfloat16 h0,h1,h2,h3,l0,l1,l2,l3;
    bsplit(v.x,h0,l0); bsplit(v.y,h1,l1); bsplit(v.z,h2,l2); bsplit(v.w,h3,l3);
    __nv_bfloat162 hp0, hp1, lp0, lp1;
    hp0.x=h0; hp0.y=h1; hp1.x=h2; hp1.y=h3;
    lp0.x=l0; lp0.y=l1; lp1.x=l2; lp1.y=l3;
    ((__nv_bfloat162*)hi)[2*i] = hp0; ((__nv_bfloat162*)hi)[2*i+1] = hp1;
    ((__nv_bfloat162*)lo)[2*i] = lp0; ((__nv_bfloat162*)lo)[2*i+1] = lp1;
}

__global__ void tsplit_kernel(const float* __restrict__ src,
                              __nv_bfloat16* __restrict__ dhi,
                              __nv_bfloat16* __restrict__ dlo, int R, int C)
{
    __shared__ float t[32][33];
    int c0 = blockIdx.x * 32, r0 = blockIdx.y * 32;
    int x = threadIdx.x, y = threadIdx.y;
    #pragma unroll
    for (int i = 0; i < 32; i += 8)
        t[y + i][x] = src[(size_t)(r0 + y + i) * C + c0 + x];
    __syncthreads();
    #pragma unroll
    for (int i = 0; i < 32; i += 8) {
        float v = t[x][y + i];
        __nv_bfloat16 h, l; bsplit(v, h, l);
        size_t o = (size_t)(c0 + y + i) * R + r0 + x;
        dhi[o] = h; dlo[o] = l;
    }
}

// ============================================================================
// 3xBF16 mma GEMM (R10 config: CTA 128x128, BK=32, 512 thr, 3-stage).
// mode 0: plain fp32 C.  mode 1: fused rope+split epilogue (packed stores).
// ============================================================================
#define STG 40960
#define OFF_AHI 0
#define OFF_ALO 10240
#define OFF_BHI 20480
#define OFF_BLO 30720
#define GSMEM (3 * STG)
#define STF 132

__global__ __launch_bounds__(512) void gemm_bf16x3_kernel(
    const __nv_bfloat16* __restrict__ Ahi, const __nv_bfloat16* __restrict__ Alo,
    const __nv_bfloat16* __restrict__ Bhi, const __nv_bfloat16* __restrict__ Blo,
    float* __restrict__ C, int M, int N, int K, int mode)
{
    extern __shared__ char smc[];
    const uint32_t sb = smem_u32(smc);
    const int tid = threadIdx.x, lane = tid & 31, wid = tid >> 5;
    const int wm = wid & 3, wn = wid >> 2;
    const int tg = lane & 3, gp = lane >> 2;
    const int m0 = blockIdx.y * 128, n0 = blockIdx.x * 128;
    const uint32_t lrow = ((lane & 7) + ((lane >> 3) & 1) * 8) * 80
                        + (lane >> 4) * 16;
    const int q  = tid & 3;
    const int r1 = tid >> 2;

    float acc[2][4][4];
    #pragma unroll
    for (int mi = 0; mi < 2; mi++)
        #pragma unroll
        for (int ni = 0; ni < 4; ni++)
            #pragma unroll
            for (int c = 0; c < 4; c++) acc[mi][ni][c] = 0.f;

    #define ISSUE(st, k0) {                                                     \
        uint32_t sba = sb + (st) * STG + r1 * 80 + q * 16;                      \
        size_t goA = (size_t)(m0 + r1) * K + (k0) + q * 8;                      \
        size_t goB = (size_t)(n0 + r1) * K + (k0) + q * 8;                      \
        cpa16(sba + OFF_AHI, Ahi + goA);                                        \
        cpa16(sba + OFF_ALO, Alo + goA);                                        \
        cpa16(sba + OFF_BHI, Bhi + goB);                                        \
        cpa16(sba + OFF_BLO, Blo + goB); }

    #define CMT asm volatile("cp.async.commit_group;" ::: "memory")

    ISSUE(0, 0);  CMT;
    ISSUE(1, 32); CMT;

    const int nst = K / 32;
    for (int s = 0; s < nst; s++) {
        asm volatile("cp.async.wait_group 1;" ::: "memory");
        __syncthreads();
        if (s + 2 < nst) { ISSUE((s + 2) % 3, (s + 2) * 32); }
        CMT;

        const uint32_t sbase = sb + (s % 3) * STG;
        #pragma unroll
        for (int ks = 0; ks < 2; ks++) {
            uint32_t Ah[2][4], Al[2][4], Bh[2][4], Bl[2][4];
            const uint32_t kso = ks * 32 + lrow;
            #pragma unroll
            for (int mi = 0; mi < 2; mi++) {
                uint32_t ro = (wm * 32 + mi * 16) * 80 + kso;
                LDM4(Ah[mi], sbase + OFF_AHI + ro);
                LDM4(Al[mi], sbase + OFF_ALO + ro);
            }
            #pragma unroll
            for (int g = 0; g < 2; g++) {
                uint32_t ro = (wn * 32 + g * 16) * 80 + kso;
                LDM4(Bh[g], sbase + OFF_BHI + ro);
                LDM4(Bl[g], sbase + OFF_BLO + ro);
            }
            #pragma unroll
            for (int mi = 0; mi < 2; mi++)
                #pragma unroll
                for (int ni = 0; ni < 4; ni++) {
                    const int g = ni >> 1, sl = ni & 1;
                    float* dd = acc[mi][ni];
                    mma16(dd, Ah[mi], Bh[g][sl], Bh[g][sl + 2]);
                    mma16(dd, Ah[mi], Bl[g][sl], Bl[g][sl + 2]);
                    mma16(dd, Al[mi], Bh[g][sl], Bh[g][sl + 2]);
                }
        }
    }

    if (mode == 0) {
        #pragma unroll
        for (int mi = 0; mi < 2; mi++) {
            int row = m0 + wm * 32 + mi * 16 + gp;
            #pragma unroll
            for (int ni = 0; ni < 4; ni++) {
                int col = n0 + wn * 32 + ni * 8 + 2 * tg;
                *(float2*)&C[(size_t)row * N + col] =
                    make_float2(acc[mi][ni][0], acc[mi][ni][1]);
                *(float2*)&C[(size_t)(row + 8) * N + col] =
                    make_float2(acc[mi][ni][2], acc[mi][ni][3]);
            }
        }
    } else {
        // Fused rope + hi/lo split epilogue; packed 4-byte stores.
        __syncthreads();
        float* st = (float*)smc;
        #pragma unroll
        for (int mi = 0; mi < 2; mi++) {
            int row = wm * 32 + mi * 16 + gp;
            #pragma unroll
            for (int ni = 0; ni < 4; ni++) {
                int col = wn * 32 + ni * 8 + 2 * tg;
                *(float2*)&st[row * STF + col] =
                    make_float2(acc[mi][ni][0], acc[mi][ni][1]);
                *(float2*)&st[(row + 8) * STF + col] =
                    make_float2(acc[mi][ni][2], acc[mi][ni][3]);
            }
        }
        __syncthreads();

        // 128 rows x 2 heads x 16 adjacent-i pairs = 4096 work items
        for (int e = tid; e < 4096; e += 512) {
            int row  = e >> 5;
            int hcol = (e >> 4) & 1;
            int i0   = (e & 15) * 2;
            int grow = m0 + row;
            int s    = grow & (S - 1);
            int b    = grow >> 11;
            int gcol = n0 + hcol * 64;
            int region = gcol >> 10;            // 0=q 1=k 2=v
            int hh     = (gcol & 1023) >> 6;    // head

            const float* sr = st + row * STF + hcol * 64;
            float a0 = sr[i0],      a1 = sr[i0 + 1];
            float b0 = sr[i0 + 32], b1 = sr[i0 + 33];
            size_t o = ((size_t)(b * H + hh) * S + s) * 64 + i0;

            float o0a, o0b, o1a, o1b;   // outputs at i0,i0+1 and i0+32,i0+33
            if (region == 2) {
                o0a = a0; o0b = a1; o1a = b0; o1b = b1;
            } else {
                float c0 = g_cost[(s << 5) + i0], sn0 = g_sint[(s << 5) + i0];
                float c1 = g_cost[(s << 5) + i0 + 1], sn1 = g_sint[(s << 5) + i0 + 1];
                o0a = a0 * c0 - b0 * sn0;  o1a = a0 * sn0 + b0 * c0;
                o0b = a1 * c1 - b1 * sn1;  o1b = a1 * sn1 + b1 * c1;
            }

            __nv_bfloat16 h0a, l0a, h0b, l0b, h1a, l1a, h1b, l1b;
            bsplit(o0a, h0a, l0a); bsplit(o0b, h0b, l0b);
            bsplit(o1a, h1a, l1a); bsplit(o1b, h1b, l1b);

            __nv_bfloat16* dh = (region == 0) ? g_sqh : (region == 1) ? g_skh : g_svh;
            __nv_bfloat16* dl = (region == 0) ? g_sql : (region == 1) ? g_skl : g_svl;
            *(uint32_t*)(dh + o)      = pack2h(h0a, h0b);
            *(uint32_t*)(dh + o + 32) = pack2h(h1a, h1b);
            *(uint32_t*)(dl + o)      = pack2h(l0a, l0b);
            *(uint32_t*)(dl + o + 32) = pack2h(l1a, l1b);
        }
    }
    #undef ISSUE
    #undef CMT
}

// ============================================================================
// RoPE tables (fp32)
// ============================================================================
__global__ void rope_table_kernel()
{
    int idx = blockIdx.x * blockDim.x + threadIdx.x;
    if (idx >= S * 32) return;
    int i = idx & 31;
    int s = idx >> 5;
    float inv = 1.0f / powf(10000.0f, (float)(2 * i) / 64.0f);
    float ang = (float)s * inv;
    float sn, c;
    sincosf(ang, &sn, &c);
    g_cost[idx] = c;
    g_sint[idx] = sn;
}

// ============================================================================
// Tensor-core split-KV flash (frozen R10 config).
// ============================================================================
#define FSTR 144
#define FT (128 * FSTR)
#define FOQH (0 * FT)
#define FOQL (1 * FT)
#define FOKH (2 * FT)
#define FOKL (3 * FT)
#define FOVH (4 * FT)
#define FOVL (5 * FT)
#define FOMSK (6 * FT)
#define FSMEM (6 * FT + 128)

__global__ __launch_bounds__(256) void flash_mma_kernel(
    const unsigned char* __restrict__ mask, const int* __restrict__ is_causal_p)
{
    extern __shared__ char smc[];
    const uint32_t sb = smem_u32(smc);

    const int qt = blockIdx.x;
    const int ch = blockIdx.y;
    const int bz = blockIdx.z;
    const int b  = bz >> 4;
    const int h  = bz & (H - 1);
    const bool causal = (*is_causal_p) != 0;
    if (causal && ch > qt) return;

    const int tid = threadIdx.x, lane = tid & 31, wid = tid >> 5;
    const int tg = lane & 3, gp = lane >> 2;
    const float scale = 0.125f;

    const size_t qb = ((size_t)bz * S + qt * 128) * 64;
    const size_t kb = ((size_t)bz * S + ch * 128) * 64;
    for (int t = tid; t < 1024; t += 256) {
        int r = t >> 3, c = t & 7;
        uint32_t dst = sb + r * FSTR + c * 16;
        size_t go = (size_t)r * 64 + c * 8;
        cpa16(dst + FOQH, g_sqh + qb + go);
        cpa16(dst + FOQL, g_sql + qb + go);
        cpa16(dst + FOKH, g_skh + kb + go);
        cpa16(dst + FOKL, g_skl + kb + go);
        cpa16(dst + FOVH, g_svh + kb + go);
        cpa16(dst + FOVL, g_svl + kb + go);
    }
    asm volatile("cp.async.commit_group;" ::: "memory");
    if (!causal && tid < 128)
        *(unsigned char*)(smc + FOMSK + tid) = mask[b * S + ch * 128 + tid];
    asm volatile("cp.async.wait_group 0;" ::: "memory");
    __syncthreads();

    const uint32_t lrowA = ((lane & 7) + ((lane >> 3) & 1) * 8) * FSTR
                         + (lane >> 4) * 16;

    uint32_t Qh[4][4], Ql[4][4];
    #pragma unroll
    for (int ks = 0; ks < 4; ks++) {
        uint32_t ro = (wid * 16) * FSTR + ks * 32 + lrowA;
        LDM4(Qh[ks], sb + FOQH + ro);
        LDM4(Ql[ks], sb + FOQL + ro);
    }

    float acc[16][4];
    #pragma unroll
    for (int ni = 0; ni < 16; ni++)
        #pragma unroll
        for (int c = 0; c < 4; c++) acc[ni][c] = 0.f;

    #pragma unroll
    for (int g = 0; g < 8; g++) {
        #pragma unroll
        for (int ks = 0; ks < 4; ks++) {
            uint32_t Kh4[4], Kl4[4];
            uint32_t ro = (g * 16) * FSTR + ks * 32 + lrowA;
            LDM4(Kh4, sb + FOKH + ro);
            LDM4(Kl4, sb + FOKL + ro);
            #pragma unroll
            for (int sl = 0; sl < 2; sl++) {
                float* dd = acc[g * 2 + sl];
                mma16(dd, Qh[ks], Kh4[sl], Kh4[sl + 2]);
                mma16(dd, Qh[ks], Kl4[sl], Kl4[sl + 2]);
                mma16(dd, Ql[ks], Kh4[sl], Kh4[sl + 2]);
            }
        }
    }

    const int qi0 = qt * 128 + wid * 16 + gp;
    float l0 = 0.f, l1 = 0.f;
    #pragma unroll
    for (int ni = 0; ni < 16; ni++) {
        #pragma unroll
        for (int e = 0; e < 2; e++) {
            int colg = ch * 128 + ni * 8 + 2 * tg + e;
            bool mv = causal ? true
                             : (*(unsigned char*)(smc + FOMSK + ni*8 + 2*tg + e) != 0);
            float p0 = (causal ? (colg <= qi0)     : mv)
                       ? __expf(acc[ni][e] * scale) : 0.f;
            float p1 = (causal ? (colg <= qi0 + 8) : mv)
                       ? __expf(acc[ni][e + 2] * scale) : 0.f;
            acc[ni][e] = p0; acc[ni][e + 2] = p1;
            l0 += p0; l1 += p1;
        }
    }
    l0 += __shfl_xor_sync(0xFFFFFFFF, l0, 1);
    l0 += __shfl_xor_sync(0xFFFFFFFF, l0, 2);
    l1 += __shfl_xor_sync(0xFFFFFFFF, l1, 1);
    l1 += __shfl_xor_sync(0xFFFFFFFF, l1, 2);
    if (tg == 0) {
        g_lpart[((size_t)ch * BS + b * S + qi0)     * H + h] = l0;
        g_lpart[((size_t)ch * BS + b * S + qi0 + 8) * H + h] = l1;
    }

    float accv[8][4];
    #pragma unroll
    for (int ni = 0; ni < 8; ni++)
        #pragma unroll
        for (int c = 0; c < 4; c++) accv[ni][c] = 0.f;

    #pragma unroll
    for (int kt = 0; kt < 8; kt++) {
        uint32_t Ph[4], Pl[4];
        #pragma unroll
        for (int half = 0; half < 2; half++) {
            const float* a = acc[2 * kt + half];
            #pragma unroll
            for (int rr = 0; rr < 2; rr++) {
                float pa = a[rr * 2], pb = a[rr * 2 + 1];
                __nv_bfloat16 ha = __float2bfloat16(pa);
                __nv_bfloat16 hb = __float2bfloat16(pb);
                float la = pa - __bfloat162float(ha);
                float lb = pb - __bfloat162float(hb);
                __nv_bfloat162 hp; hp.x = ha; hp.y = hb;
                Ph[half * 2 + rr] = *(uint32_t*)&hp;
                Pl[half * 2 + rr] = packbf(la, lb);
            }
        }
        #pragma unroll
        for (int g2 = 0; g2 < 4; g2++) {
            uint32_t Vh4[4], Vl4[4];
            uint32_t ro = (kt * 16 + (lane & 15)) * FSTR
                        + g2 * 32 + (lane >> 4) * 16;
            LDM4T(Vh4, sb + FOVH + ro);
            LDM4T(Vl4, sb + FOVL + ro);
            #pragma unroll
            for (int sl = 0; sl < 2; sl++) {
                float* dd = accv[g2 * 2 + sl];
                mma16(dd, Ph, Vh4[sl * 2], Vh4[sl * 2 + 1]);
                mma16(dd, Ph, Vl4[sl * 2], Vl4[sl * 2 + 1]);
                mma16(dd, Pl, Vh4[sl * 2], Vh4[sl * 2 + 1]);
            }
        }
    }

    float* p0 = g_part + ((size_t)ch * BS + b * S + qi0)     * D + h * DH;
    float* p1 = g_part + ((size_t)ch * BS + b * S + qi0 + 8) * D + h * DH;
    #pragma unroll
    for (int ni = 0; ni < 8; ni++) {
        int d = ni * 8 + 2 * tg;
        *(float2*)(p0 + d) = make_float2(accv[ni][0], accv[ni][1]);
        *(float2*)(p1 + d) = make_float2(accv[ni][2], accv[ni][3]);
    }
}

// ============================================================================
// Reduce partials -> attn as split bf16 (hi/lo)
// ============================================================================
__global__ void flash_reduce_kernel(const int* __restrict__ is_causal_p)
{
    int idx = blockIdx.x * blockDim.x + threadIdx.x;
    if (idx >= BS * D / 4) return;
    int base = idx * 4;
    int qrow = base / D;
    int d    = base % D;
    int h    = d >> 6;
    int q    = qrow & (S - 1);
    const int nv = (*is_causal_p) ? ((q >> 7) + 1) : NCH;

    float4 acc = make_float4(0.f, 0.f, 0.f, 0.f);
    float l = 0.f;
    for (int c = 0; c < nv; c++) {
        const float4 p = *(const float4*)(g_part + ((size_t)c * BS + qrow) * D + d);
        acc.x += p.x; acc.y += p.y; acc.z += p.z; acc.w += p.w;
        l += g_lpart[((size_t)c * BS + qrow) * H + h];
    }
    float inv = 1.f / l;
    float o0 = acc.x*inv, o1 = acc.y*inv, o2 = acc.z*inv, o3 = acc.w*inv;

    __nv_bfloat16 h0,h1,h2,h3,l0,l1,l2,l3;
    bsplit(o0,h0,l0); bsplit(o1,h1,l1); bsplit(o2,h2,l2); bsplit(o3,h3,l3);
    size_t o = (size_t)qrow * D + d;
    __nv_bfloat162 t;
    t.x=h0; t.y=h1; *(__nv_bfloat162*)(g_ahi + o)     = t;
    t.x=h2; t.y=h3; *(__nv_bfloat162*)(g_ahi + o + 2) = t;
    t.x=l0; t.y=l1; *(__nv_bfloat162*)(g_alo + o)     = t;
    t.x=l2; t.y=l3; *(__nv_bfloat162*)(g_alo + o + 2) = t;
}

// ============================================================================
extern "C" void kernel_launch(void* const* d_in, const int* in_sizes, int n_in,
                              void* d_out, int out_size)
{
    const float* x      = (const float*)d_in[0];
    const float* qkv_w  = (const float*)d_in[1];
    const float* out_w  = (const float*)d_in[2];
    const unsigned char* mask = (const unsigned char*)d_in[3];
    const int* is_causal = (const int*)d_in[4];
    float* out = (float*)d_out;

    __nv_bfloat16 *xhi, *xlo, *wqh, *wql, *woh, *wol, *ahi, *alo;
    cudaGetSymbolAddress((void**)&xhi, g_xhi);
    cudaGetSymbolAddress((void**)&xlo, g_xlo);
    cudaGetSymbolAddress((void**)&wqh, g_wqT_hi);
    cudaGetSymbolAddress((void**)&wql, g_wqT_lo);
    cudaGetSymbolAddress((void**)&woh, g_woT_hi);
    cudaGetSymbolAddress((void**)&wol, g_woT_lo);
    cudaGetSymbolAddress((void**)&ahi, g_ahi);
    cudaGetSymbolAddress((void**)&alo, g_alo);

    cudaFuncSetAttribute(gemm_bf16x3_kernel,
                         cudaFuncAttributeMaxDynamicSharedMemorySize, GSMEM);
    cudaFuncSetAttribute(flash_mma_kernel,
                         cudaFuncAttributeMaxDynamicSharedMemorySize, FSMEM);

    // 0) Pre-splits + rope table (table must precede the fused QKV epilogue)
    split_kernel<<<(BS * D / 4 + 255) / 256, 256>>>(x, xhi, xlo, BS * D / 4);
    tsplit_kernel<<<dim3(D3 / 32, D / 32), dim3(32, 8)>>>(qkv_w, wqh, wql, D, D3);
    tsplit_kernel<<<dim3(D  / 32, D / 32), dim3(32, 8)>>>(out_w, woh, wol, D, D);
    rope_table_kernel<<<(S * 32 + 255) / 256, 256>>>();

    // 1) QKV projection with fused rope+split epilogue (mode 1)
    gemm_bf16x3_kernel<<<dim3(D3 / 128, BS / 128), 512, GSMEM>>>(
        xhi, xlo, wqh, wql, nullptr, BS, D3, D, 1);

    // 2) Flash (CHK=128) + reduce
    flash_mma_kernel<<<dim3(S / 128, NCH, B * H), 256, FSMEM>>>(mask, is_causal);
    flash_reduce_kernel<<<(BS * D / 4 + 255) / 256, 256>>>(is_causal);

    // 3) Output projection (mode 0)
    gemm_bf16x3_kernel<<<dim3(D / 128, BS / 128), 512, GSMEM>>>(
        ahi, alo, woh, wol, out, BS, D, D, 0);
}

// round 16
// speedup vs baseline: 1.6352x; 1.0023x over previous
#include <cuda_runtime.h>
#include <cuda_bf16.h>
#include <math.h>
#include <stdint.h>

#define B 2
#define S 2048
#define D 1024
#define H 16
#define DH 64
#define BS (B*S)     /* 4096 */
#define D3 (3*D)     /* 3072 */
#define NCH 16       /* key chunks */
#define CHK 128      /* keys per chunk */

// Scratch (allocation-free rule: __device__ globals)
__device__ float g_part[(size_t)NCH * BS * D];   // 256 MB
__device__ float g_lpart[(size_t)NCH * BS * H];  // 4 MB
__device__ float g_cost[S * 32];
__device__ float g_sint[S * 32];
__device__ __nv_bfloat16 g_xhi[BS * D],  g_xlo[BS * D];
__device__ __nv_bfloat16 g_wqT_hi[D3 * D], g_wqT_lo[D3 * D];
__device__ __nv_bfloat16 g_woT_hi[D * D],  g_woT_lo[D * D];
__device__ __nv_bfloat16 g_ahi[BS * D],  g_alo[BS * D];
// roped q,k and v, split bf16, layout [b][h][s][64]
__device__ __nv_bfloat16 g_sqh[BS * D], g_sql[BS * D];
__device__ __nv_bfloat16 g_skh[BS * D], g_skl[BS * D];
__device__ __nv_bfloat16 g_svh[BS * D], g_svl[BS * D];

// ============================================================================
// Helpers
// ============================================================================
__device__ __forceinline__ uint32_t smem_u32(const void* p) {
    uint32_t a;
    asm("{ .reg .u64 t; cvta.to.shared.u64 t, %1; cvt.u32.u64 %0, t; }"
        : "=r"(a) : "l"(p));
    return a;
}
__device__ __forceinline__ void bsplit(float v, __nv_bfloat16& h, __nv_bfloat16& l) {
    h = __float2bfloat16(v);
    l = __float2bfloat16(v - __bfloat162float(h));
}
__device__ __forceinline__ uint32_t packbf(float a, float b) {
    __nv_bfloat162 t = __floats2bfloat162_rn(a, b);
    return *(uint32_t*)&t;
}
__device__ __forceinline__ uint32_t pack2h(__nv_bfloat16 a, __nv_bfloat16 b) {
    __nv_bfloat162 t; t.x = a; t.y = b;
    return *(uint32_t*)&t;
}
__device__ __forceinline__ void cpa16(uint32_t s, const void* g) {
    uint64_t ga;
    asm("cvta.to.global.u64 %0, %1;" : "=l"(ga) : "l"(g));
    asm volatile("cp.async.cg.shared.global [%0], [%1], 16;"
                 :: "r"(s), "l"(ga) : "memory");
}
__device__ __forceinline__ void mma16(float* d, const uint32_t* a,
                                      uint32_t b0, uint32_t b1) {
    asm volatile(
        "mma.sync.aligned.m16n8k16.row.col.f32.bf16.bf16.f32 "
        "{%0,%1,%2,%3}, {%4,%5,%6,%7}, {%8,%9}, {%0,%1,%2,%3};"
        : "+f"(d[0]), "+f"(d[1]), "+f"(d[2]), "+f"(d[3])
        : "r"(a[0]), "r"(a[1]), "r"(a[2]), "r"(a[3]), "r"(b0), "r"(b1));
}
#define LDM4(r, addr) \
    asm volatile("ldmatrix.sync.aligned.m8n8.x4.shared.b16 {%0,%1,%2,%3}, [%4];" \
        : "=r"((r)[0]), "=r"((r)[1]), "=r"((r)[2]), "=r"((r)[3]) : "r"(addr))
#define LDM4T(r, addr) \
    asm volatile("ldmatrix.sync.aligned.m8n8.x4.trans.shared.b16 {%0,%1,%2,%3}, [%4];" \
        : "=r"((r)[0]), "=r"((r)[1]), "=r"((r)[2]), "=r"((r)[3]) : "r"(addr))

// ============================================================================
// Split kernels
// ============================================================================
__global__ void split_kernel(const float* __restrict__ src,
                             __nv_bfloat16* __restrict__ hi,
                             __nv_bfloat16* __restrict__ lo, int n4)
{
    int i = blockIdx.x * blockDim.x + threadIdx.x;
    if (i >= n4) return;
    float4 v = ((const float4*)src)[i];
    __nv_bfloat16 h0,h1,h2,h3,l0,l1,l2,l3;
    bsplit(v.x,h0,l0); bsplit(v.y,h1,l1); bsplit(v.z,h2,l2); bsplit(v.w,h3,l3);
    __nv_bfloat162 hp0, hp1, lp0, lp1;
    hp0.x=h0; hp0.y=h1; hp1.x=h2; hp1.y=h3;
    lp0.x=l0; lp0.y=l1; lp1.x=l2; lp1.y=l3;
    ((__nv_bfloat162*)hi)[2*i] = hp0; ((__nv_bfloat162*)hi)[2*i+1] = hp1;
    ((__nv_bfloat162*)lo)[2*i] = lp0; ((__nv_bfloat162*)lo)[2*i+1] = lp1;
}

__global__ void tsplit_kernel(const float* __restrict__ src,
                              __nv_bfloat16* __restrict__ dhi,
                              __nv_bfloat16* __restrict__ dlo, int R, int C)
{
    __shared__ float t[32][33];
    int c0 = blockIdx.x * 32, r0 = blockIdx.y * 32;
    int x = threadIdx.x, y = threadIdx.y;
    #pragma unroll
    for (int i = 0; i < 32; i += 8)
        t[y + i][x] = src[(size_t)(r0 + y + i) * C + c0 + x];
    __syncthreads();
    #pragma unroll
    for (int i = 0; i < 32; i += 8) {
        float v = t[x][y + i];
        __nv_bfloat16 h, l; bsplit(v, h, l);
        size_t o = (size_t)(c0 + y + i) * R + r0 + x;
        dhi[o] = h; dlo[o] = l;
    }
}

// ============================================================================
// 3xBF16 mma GEMM (R10 config: CTA 128x128, BK=32, 512 thr, 3-stage).
// mode 0: plain fp32 C.  mode 1: fused rope+split epilogue (packed stores).
// ============================================================================
#define STG 40960
#define OFF_AHI 0
#define OFF_ALO 10240
#define OFF_BHI 20480
#define OFF_BLO 30720
#define GSMEM (3 * STG)
#define STF 132

__global__ __launch_bounds__(512) void gemm_bf16x3_kernel(
    const __nv_bfloat16* __restrict__ Ahi, const __nv_bfloat16* __restrict__ Alo,
    const __nv_bfloat16* __restrict__ Bhi, const __nv_bfloat16* __restrict__ Blo,
    float* __restrict__ C, int M, int N, int K, int mode)
{
    extern __shared__ char smc[];
    const uint32_t sb = smem_u32(smc);
    const int tid = threadIdx.x, lane = tid & 31, wid = tid >> 5;
    const int wm = wid & 3, wn = wid >> 2;
    const int tg = lane & 3, gp = lane >> 2;
    const int m0 = blockIdx.y * 128, n0 = blockIdx.x * 128;
    const uint32_t lrow = ((lane & 7) + ((lane >> 3) & 1) * 8) * 80
                        + (lane >> 4) * 16;
    const int q  = tid & 3;
    const int r1 = tid >> 2;

    float acc[2][4][4];
    #pragma unroll
    for (int mi = 0; mi < 2; mi++)
        #pragma unroll
        for (int ni = 0; ni < 4; ni++)
            #pragma unroll
            for (int c = 0; c < 4; c++) acc[mi][ni][c] = 0.f;

    #define ISSUE(st, k0) {                                                     \
        uint32_t sba = sb + (st) * STG + r1 * 80 + q * 16;                      \
        size_t goA = (size_t)(m0 + r1) * K + (k0) + q * 8;                      \
        size_t goB = (size_t)(n0 + r1) * K + (k0) + q * 8;                      \
        cpa16(sba + OFF_AHI, Ahi + goA);                                        \
        cpa16(sba + OFF_ALO, Alo + goA);                                        \
        cpa16(sba + OFF_BHI, Bhi + goB);                                        \
        cpa16(sba + OFF_BLO, Blo + goB); }

    #define CMT asm volatile("cp.async.commit_group;" ::: "memory")

    ISSUE(0, 0);  CMT;
    ISSUE(1, 32); CMT;

    const int nst = K / 32;
    for (int s = 0; s < nst; s++) {
        asm volatile("cp.async.wait_group 1;" ::: "memory");
        __syncthreads();
        if (s + 2 < nst) { ISSUE((s + 2) % 3, (s + 2) * 32); }
        CMT;

        const uint32_t sbase = sb + (s % 3) * STG;
        #pragma unroll
        for (int ks = 0; ks < 2; ks++) {
            uint32_t Ah[2][4], Al[2][4], Bh[2][4], Bl[2][4];
            const uint32_t kso = ks * 32 + lrow;
            #pragma unroll
            for (int mi = 0; mi < 2; mi++) {
                uint32_t ro = (wm * 32 + mi * 16) * 80 + kso;
                LDM4(Ah[mi], sbase + OFF_AHI + ro);
                LDM4(Al[mi], sbase + OFF_ALO + ro);
            }
            #pragma unroll
            for (int g = 0; g < 2; g++) {
                uint32_t ro = (wn * 32 + g * 16) * 80 + kso;
                LDM4(Bh[g], sbase + OFF_BHI + ro);
                LDM4(Bl[g], sbase + OFF_BLO + ro);
            }
            #pragma unroll
            for (int mi = 0; mi < 2; mi++)
                #pragma unroll
                for (int ni = 0; ni < 4; ni++) {
                    const int g = ni >> 1, sl = ni & 1;
                    float* dd = acc[mi][ni];
                    mma16(dd, Ah[mi], Bh[g][sl], Bh[g][sl + 2]);
                    mma16(dd, Ah[mi], Bl[g][sl], Bl[g][sl + 2]);
                    mma16(dd, Al[mi], Bh[g][sl], Bh[g][sl + 2]);
                }
        }
    }

    if (mode == 0) {
        #pragma unroll
        for (int mi = 0; mi < 2; mi++) {
            int row = m0 + wm * 32 + mi * 16 + gp;
            #pragma unroll
            for (int ni = 0; ni < 4; ni++) {
                int col = n0 + wn * 32 + ni * 8 + 2 * tg;
                *(float2*)&C[(size_t)row * N + col] =
                    make_float2(acc[mi][ni][0], acc[mi][ni][1]);
                *(float2*)&C[(size_t)(row + 8) * N + col] =
                    make_float2(acc[mi][ni][2], acc[mi][ni][3]);
            }
        }
    } else {
        // Fused rope + hi/lo split epilogue; packed 4-byte stores.
        __syncthreads();
        float* st = (float*)smc;
        #pragma unroll
        for (int mi = 0; mi < 2; mi++) {
            int row = wm * 32 + mi * 16 + gp;
            #pragma unroll
            for (int ni = 0; ni < 4; ni++) {
                int col = wn * 32 + ni * 8 + 2 * tg;
                *(float2*)&st[row * STF + col] =
                    make_float2(acc[mi][ni][0], acc[mi][ni][1]);
                *(float2*)&st[(row + 8) * STF + col] =
                    make_float2(acc[mi][ni][2], acc[mi][ni][3]);
            }
        }
        __syncthreads();

        // 128 rows x 2 heads x 16 adjacent-i pairs = 4096 work items
        for (int e = tid; e < 4096; e += 512) {
            int row  = e >> 5;
            int hcol = (e >> 4) & 1;
            int i0   = (e & 15) * 2;
            int grow = m0 + row;
            int s    = grow & (S - 1);
            int b    = grow >> 11;
            int gcol = n0 + hcol * 64;
            int region = gcol >> 10;            // 0=q 1=k 2=v
            int hh     = (gcol & 1023) >> 6;    // head

            const float* sr = st + row * STF + hcol * 64;
            float a0 = sr[i0],      a1 = sr[i0 + 1];
            float b0 = sr[i0 + 32], b1 = sr[i0 + 33];
            size_t o = ((size_t)(b * H + hh) * S + s) * 64 + i0;

            float o0a, o0b, o1a, o1b;
            if (region == 2) {
                o0a = a0; o0b = a1; o1a = b0; o1b = b1;
            } else {
                float c0 = g_cost[(s << 5) + i0], sn0 = g_sint[(s << 5) + i0];
                float c1 = g_cost[(s << 5) + i0 + 1], sn1 = g_sint[(s << 5) + i0 + 1];
                o0a = a0 * c0 - b0 * sn0;  o1a = a0 * sn0 + b0 * c0;
                o0b = a1 * c1 - b1 * sn1;  o1b = a1 * sn1 + b1 * c1;
            }

            __nv_bfloat16 h0a, l0a, h0b, l0b, h1a, l1a, h1b, l1b;
            bsplit(o0a, h0a, l0a); bsplit(o0b, h0b, l0b);
            bsplit(o1a, h1a, l1a); bsplit(o1b, h1b, l1b);

            __nv_bfloat16* dh = (region == 0) ? g_sqh : (region == 1) ? g_skh : g_svh;
            __nv_bfloat16* dl = (region == 0) ? g_sql : (region == 1) ? g_skl : g_svl;
            *(uint32_t*)(dh + o)      = pack2h(h0a, h0b);
            *(uint32_t*)(dh + o + 32) = pack2h(h1a, h1b);
            *(uint32_t*)(dl + o)      = pack2h(l0a, l0b);
            *(uint32_t*)(dl + o + 32) = pack2h(l1a, l1b);
        }
    }
    #undef ISSUE
    #undef CMT
}

// ============================================================================
// RoPE tables (fp32)
// ============================================================================
__global__ void rope_table_kernel()
{
    int idx = blockIdx.x * blockDim.x + threadIdx.x;
    if (idx >= S * 32) return;
    int i = idx & 31;
    int s = idx >> 5;
    float inv = 1.0f / powf(10000.0f, (float)(2 * i) / 64.0f);
    float ang = (float)s * inv;
    float sn, c;
    sincosf(ang, &sn, &c);
    g_cost[idx] = c;
    g_sint[idx] = sn;
}

// ============================================================================
// Tensor-core split-KV flash (frozen R10 config).
// ============================================================================
#define FSTR 144
#define FT (128 * FSTR)
#define FOQH (0 * FT)
#define FOQL (1 * FT)
#define FOKH (2 * FT)
#define FOKL (3 * FT)
#define FOVH (4 * FT)
#define FOVL (5 * FT)
#define FOMSK (6 * FT)
#define FSMEM (6 * FT + 128)

__global__ __launch_bounds__(256) void flash_mma_kernel(
    const unsigned char* __restrict__ mask, const int* __restrict__ is_causal_p)
{
    extern __shared__ char smc[];
    const uint32_t sb = smem_u32(smc);

    const int qt = blockIdx.x;
    const int ch = blockIdx.y;
    const int bz = blockIdx.z;
    const int b  = bz >> 4;
    const int h  = bz & (H - 1);
    const bool causal = (*is_causal_p) != 0;
    if (causal && ch > qt) return;

    const int tid = threadIdx.x, lane = tid & 31, wid = tid >> 5;
    const int tg = lane & 3, gp = lane >> 2;
    const float scale = 0.125f;

    const size_t qb = ((size_t)bz * S + qt * 128) * 64;
    const size_t kb = ((size_t)bz * S + ch * 128) * 64;
    for (int t = tid; t < 1024; t += 256) {
        int r = t >> 3, c = t & 7;
        uint32_t dst = sb + r * FSTR + c * 16;
        size_t go = (size_t)r * 64 + c * 8;
        cpa16(dst + FOQH, g_sqh + qb + go);
        cpa16(dst + FOQL, g_sql + qb + go);
        cpa16(dst + FOKH, g_skh + kb + go);
        cpa16(dst + FOKL, g_skl + kb + go);
        cpa16(dst + FOVH, g_svh + kb + go);
        cpa16(dst + FOVL, g_svl + kb + go);
    }
    asm volatile("cp.async.commit_group;" ::: "memory");
    if (!causal && tid < 128)
        *(unsigned char*)(smc + FOMSK + tid) = mask[b * S + ch * 128 + tid];
    asm volatile("cp.async.wait_group 0;" ::: "memory");
    __syncthreads();

    const uint32_t lrowA = ((lane & 7) + ((lane >> 3) & 1) * 8) * FSTR
                         + (lane >> 4) * 16;

    uint32_t Qh[4][4], Ql[4][4];
    #pragma unroll
    for (int ks = 0; ks < 4; ks++) {
        uint32_t ro = (wid * 16) * FSTR + ks * 32 + lrowA;
        LDM4(Qh[ks], sb + FOQH + ro);
        LDM4(Ql[ks], sb + FOQL + ro);
    }

    float acc[16][4];
    #pragma unroll
    for (int ni = 0; ni < 16; ni++)
        #pragma unroll
        for (int c = 0; c < 4; c++) acc[ni][c] = 0.f;

    #pragma unroll
    for (int g = 0; g < 8; g++) {
        #pragma unroll
        for (int ks = 0; ks < 4; ks++) {
            uint32_t Kh4[4], Kl4[4];
            uint32_t ro = (g * 16) * FSTR + ks * 32 + lrowA;
            LDM4(Kh4, sb + FOKH + ro);
            LDM4(Kl4, sb + FOKL + ro);
            #pragma unroll
            for (int sl = 0; sl < 2; sl++) {
                float* dd = acc[g * 2 + sl];
                mma16(dd, Qh[ks], Kh4[sl], Kh4[sl + 2]);
                mma16(dd, Qh[ks], Kl4[sl], Kl4[sl + 2]);
                mma16(dd, Ql[ks], Kh4[sl], Kh4[sl + 2]);
            }
        }
    }

    const int qi0 = qt * 128 + wid * 16 + gp;
    float l0 = 0.f, l1 = 0.f;
    #pragma unroll
    for (int ni = 0; ni < 16; ni++) {
        #pragma unroll
        for (int e = 0; e < 2; e++) {
            int colg = ch * 128 + ni * 8 + 2 * tg + e;
            bool mv = causal ? true
                             : (*(unsigned char*)(smc + FOMSK + ni*8 + 2*tg + e) != 0);
            float p0 = (causal ? (colg <= qi0)     : mv)
                       ? __expf(acc[ni][e] * scale) : 0.f;
            float p1 = (causal ? (colg <= qi0 + 8) : mv)
                       ? __expf(acc[ni][e + 2] * scale) : 0.f;
            acc[ni][e] = p0; acc[ni][e + 2] = p1;
            l0 += p0; l1 += p1;
        }
    }
    l0 += __shfl_xor_sync(0xFFFFFFFF, l0, 1);
    l0 += __shfl_xor_sync(0xFFFFFFFF, l0, 2);
    l1 += __shfl_xor_sync(0xFFFFFFFF, l1, 1);
    l1 += __shfl_xor_sync(0xFFFFFFFF, l1, 2);
    if (tg == 0) {
        g_lpart[((size_t)ch * BS + b * S + qi0)     * H + h] = l0;
        g_lpart[((size_t)ch * BS + b * S + qi0 + 8) * H + h] = l1;
    }

    float accv[8][4];
    #pragma unroll
    for (int ni = 0; ni < 8; ni++)
        #pragma unroll
        for (int c = 0; c < 4; c++) accv[ni][c] = 0.f;

    #pragma unroll
    for (int kt = 0; kt < 8; kt++) {
        uint32_t Ph[4], Pl[4];
        #pragma unroll
        for (int half = 0; half < 2; half++) {
            const float* a = acc[2 * kt + half];
            #pragma unroll
            for (int rr = 0; rr < 2; rr++) {
                float pa = a[rr * 2], pb = a[rr * 2 + 1];
                __nv_bfloat16 ha = __float2bfloat16(pa);
                __nv_bfloat16 hb = __float2bfloat16(pb);
                float la = pa - __bfloat162float(ha);
                float lb = pb - __bfloat162float(hb);
                __nv_bfloat162 hp; hp.x = ha; hp.y = hb;
                Ph[half * 2 + rr] = *(uint32_t*)&hp;
                Pl[half * 2 + rr] = packbf(la, lb);
            }
        }
        #pragma unroll
        for (int g2 = 0; g2 < 4; g2++) {
            uint32_t Vh4[4], Vl4[4];
            uint32_t ro = (kt * 16 + (lane & 15)) * FSTR
                        + g2 * 32 + (lane >> 4) * 16;
            LDM4T(Vh4, sb + FOVH + ro);
            LDM4T(Vl4, sb + FOVL + ro);
            #pragma unroll
            for (int sl = 0; sl < 2; sl++) {
                float* dd = accv[g2 * 2 + sl];
                mma16(dd, Ph, Vh4[sl * 2], Vh4[sl * 2 + 1]);
                mma16(dd, Ph, Vl4[sl * 2], Vl4[sl * 2 + 1]);
                mma16(dd, Pl, Vh4[sl * 2], Vh4[sl * 2 + 1]);
            }
        }
    }

    float* p0 = g_part + ((size_t)ch * BS + b * S + qi0)     * D + h * DH;
    float* p1 = g_part + ((size_t)ch * BS + b * S + qi0 + 8) * D + h * DH;
    #pragma unroll
    for (int ni = 0; ni < 8; ni++) {
        int d = ni * 8 + 2 * tg;
        *(float2*)(p0 + d) = make_float2(accv[ni][0], accv[ni][1]);
        *(float2*)(p1 + d) = make_float2(accv[ni][2], accv[ni][3]);
    }
}

// ============================================================================
// Reduce partials -> attn as split bf16 (hi/lo).
// 8 columns per thread: two independent float4 chains per chunk (2x MLP),
// single l-partial load per chunk (both quads share the head).
// ============================================================================
__global__ void flash_reduce_kernel(const int* __restrict__ is_causal_p)
{
    int idx = blockIdx.x * blockDim.x + threadIdx.x;   // over BS*D/8
    if (idx >= BS * D / 8) return;
    int base = idx * 8;
    int qrow = base / D;
    int d    = base % D;            // 8-aligned; d..d+7 within one 64-col head
    int h    = d >> 6;
    int q    = qrow & (S - 1);
    const int nv = (*is_causal_p) ? ((q >> 7) + 1) : NCH;

    float4 accA = make_float4(0.f, 0.f, 0.f, 0.f);
    float4 accB = make_float4(0.f, 0.f, 0.f, 0.f);
    float l = 0.f;
    const float* pb = g_part + (size_t)qrow * D + d;
    const float* lb = g_lpart + (size_t)qrow * H + h;
    #pragma unroll 4
    for (int c = 0; c < nv; c++) {
        const float4 pA = *(const float4*)(pb + (size_t)c * BS * D);
        const float4 pB = *(const float4*)(pb + (size_t)c * BS * D + 4);
        l += lb[(size_t)c * BS * H];
        accA.x += pA.x; accA.y += pA.y; accA.z += pA.z; accA.w += pA.w;
        accB.x += pB.x; accB.y += pB.y; accB.z += pB.z; accB.w += pB.w;
    }
    float inv = 1.f / l;

    size_t o = (size_t)qrow * D + d;
    float v0 = accA.x * inv, v1 = accA.y * inv, v2 = accA.z * inv, v3 = accA.w * inv;
    float v4 = accB.x * inv, v5 = accB.y * inv, v6 = accB.z * inv, v7 = accB.w * inv;

    __nv_bfloat16 hh[8], ll[8];
    bsplit(v0, hh[0], ll[0]); bsplit(v1, hh[1], ll[1]);
    bsplit(v2, hh[2], ll[2]); bsplit(v3, hh[3], ll[3]);
    bsplit(v4, hh[4], ll[4]); bsplit(v5, hh[5], ll[5]);
    bsplit(v6, hh[6], ll[6]); bsplit(v7, hh[7], ll[7]);

    uint4 hw, lw;
    hw.x = pack2h(hh[0], hh[1]); hw.y = pack2h(hh[2], hh[3]);
    hw.z = pack2h(hh[4], hh[5]); hw.w = pack2h(hh[6], hh[7]);
    lw.x = pack2h(ll[0], ll[1]); lw.y = pack2h(ll[2], ll[3]);
    lw.z = pack2h(ll[4], ll[5]); lw.w = pack2h(ll[6], ll[7]);
    *(uint4*)(g_ahi + o) = hw;
    *(uint4*)(g_alo + o) = lw;
}

// ============================================================================
extern "C" void kernel_launch(void* const* d_in, const int* in_sizes, int n_in,
                              void* d_out, int out_size)
{
    const float* x      = (const float*)d_in[0];
    const float* qkv_w  = (const float*)d_in[1];
    const float* out_w  = (const float*)d_in[2];
    const unsigned char* mask = (const unsigned char*)d_in[3];
    const int* is_causal = (const int*)d_in[4];
    float* out = (float*)d_out;

    __nv_bfloat16 *xhi, *xlo, *wqh, *wql, *woh, *wol, *ahi, *alo;
    cudaGetSymbolAddress((void**)&xhi, g_xhi);
    cudaGetSymbolAddress((void**)&xlo, g_xlo);
    cudaGetSymbolAddress((void**)&wqh, g_wqT_hi);
    cudaGetSymbolAddress((void**)&wql, g_wqT_lo);
    cudaGetSymbolAddress((void**)&woh, g_woT_hi);
    cudaGetSymbolAddress((void**)&wol, g_woT_lo);
    cudaGetSymbolAddress((void**)&ahi, g_ahi);
    cudaGetSymbolAddress((void**)&alo, g_alo);

    cudaFuncSetAttribute(gemm_bf16x3_kernel,
                         cudaFuncAttributeMaxDynamicSharedMemorySize, GSMEM);
    cudaFuncSetAttribute(flash_mma_kernel,
                         cudaFuncAttributeMaxDynamicSharedMemorySize, FSMEM);

    // 0) Pre-splits + rope table (table must precede the fused QKV epilogue)
    split_kernel<<<(BS * D / 4 + 255) / 256, 256>>>(x, xhi, xlo, BS * D / 4);
    tsplit_kernel<<<dim3(D3 / 32, D / 32), dim3(32, 8)>>>(qkv_w, wqh, wql, D, D3);
    tsplit_kernel<<<dim3(D  / 32, D / 32), dim3(32, 8)>>>(out_w, woh, wol, D, D);
    rope_table_kernel<<<(S * 32 + 255) / 256, 256>>>();

    // 1) QKV projection with fused rope+split epilogue (mode 1)
    gemm_bf16x3_kernel<<<dim3(D3 / 128, BS / 128), 512, GSMEM>>>(
        xhi, xlo, wqh, wql, nullptr, BS, D3, D, 1);

    // 2) Flash (CHK=128) + reduce
    flash_mma_kernel<<<dim3(S / 128, NCH, B * H), 256, FSMEM>>>(mask, is_causal);
    flash_reduce_kernel<<<(BS * D / 8 + 255) / 256, 256>>>(is_causal);

    // 3) Output projection (mode 0)
    gemm_bf16x3_kernel<<<dim3(D / 128, BS / 128), 512, GSMEM>>>(
        ahi, alo, woh, wol, out, BS, D, D, 0);
}